// round 2
// baseline (speedup 1.0000x reference)
#include <cuda_runtime.h>

// Bilinear 2x upsample, NHWC f32: (8,256,256,32) -> (8,512,512,32).
// scale = 0.5 exactly: gy = max(oy*0.5 - 0.25, 0), y0 = floor(gy), frac = gy - y0.
// One thread per (output pixel, float4 of channels): 8 threads/pixel,
// all loads/stores fully coalesced 16B per thread.

#define IH 256
#define IW 256
#define OH 512
#define OW 512
#define C4 8          // 32 channels / 4
#define NBATCH 8

__global__ __launch_bounds__(256) void bilinear2x_kernel(
    const float4* __restrict__ in, float4* __restrict__ out)
{
    const long long idx = (long long)blockIdx.x * blockDim.x + threadIdx.x;
    // total = NBATCH*OH*OW*C4 = 16,777,216 — exact multiple of grid*block; no bounds check needed
    const int c4  = (int)(idx & (C4 - 1));
    const long long pix = idx >> 3;            // / C4
    const int ox = (int)(pix & (OW - 1));
    const long long row = pix >> 9;            // / OW
    const int oy = (int)(row & (OH - 1));
    const int n  = (int)(row >> 9);            // / OH

    // Closed-form source coords for scale 0.5
    float gy = fmaxf((float)oy * 0.5f - 0.25f, 0.0f);
    float gx = fmaxf((float)ox * 0.5f - 0.25f, 0.0f);
    int y0 = (int)gy;                 // gy >= 0, truncation == floor
    int x0 = (int)gx;
    float h0 = gy - (float)y0;
    float w0 = gx - (float)x0;
    int y1 = y0 + (y0 < IH - 1);
    int x1 = x0 + (x0 < IW - 1);
    float h1 = 1.0f - h0;
    float w1 = 1.0f - w0;

    // Bilinear weights
    float a00 = h1 * w1;
    float a01 = h1 * w0;
    float a10 = h0 * w1;
    float a11 = h0 * w0;

    const long long nbase = (long long)n * (IH * IW * C4);
    const float4 v00 = __ldg(&in[nbase + ((long long)y0 * IW + x0) * C4 + c4]);
    const float4 v01 = __ldg(&in[nbase + ((long long)y0 * IW + x1) * C4 + c4]);
    const float4 v10 = __ldg(&in[nbase + ((long long)y1 * IW + x0) * C4 + c4]);
    const float4 v11 = __ldg(&in[nbase + ((long long)y1 * IW + x1) * C4 + c4]);

    float4 r;
    r.x = h1 * (w1 * v00.x + w0 * v01.x) + h0 * (w1 * v10.x + w0 * v11.x);
    r.y = h1 * (w1 * v00.y + w0 * v01.y) + h0 * (w1 * v10.y + w0 * v11.y);
    r.z = h1 * (w1 * v00.z + w0 * v01.z) + h0 * (w1 * v10.z + w0 * v11.z);
    r.w = h1 * (w1 * v00.w + w0 * v01.w) + h0 * (w1 * v10.w + w0 * v11.w);

    out[idx] = r;
    (void)a00; (void)a01; (void)a10; (void)a11;
}

extern "C" void kernel_launch(void* const* d_in, const int* in_sizes, int n_in,
                              void* d_out, int out_size)
{
    const float4* in  = (const float4*)d_in[0];
    float4*       out = (float4*)d_out;
    const long long total = (long long)NBATCH * OH * OW * C4;  // 16,777,216
    const int threads = 256;
    const long long blocks = total / threads;                   // 65,536
    bilinear2x_kernel<<<(unsigned)blocks, threads>>>(in, out);
}

// round 5
// speedup vs baseline: 1.3868x; 1.3868x over previous
#include <cuda_runtime.h>

// Bilinear 2x upsample NHWC f32: (8,256,256,32) -> (8,512,512,32).
// Quad kernel: each thread produces a 2x2 output pixel quad from one 2x2
// input patch (per float4 channel group). Fixed fractions for scale 0.5:
// odd output row: h0=0.25, even row: h0=0.75; rows (2k-1, 2k) share input
// rows (k-1, k). Edges handled by index clamping (degenerate patches have
// equal loaded values, so result is exact regardless of weight).

#define IH 256
#define IW 256
#define OH 512
#define OW 512
#define C4 8          // 32 channels / 4 floats

__global__ __launch_bounds__(256) void bilinear2x_quad_kernel(
    const float4* __restrict__ in, float4* __restrict__ out)
{
    // threadIdx.x: [c4:3][jloc:5] -> 8 channel-groups x 32 x-quads per block
    const int c4   = threadIdx.x & (C4 - 1);
    const int j    = blockIdx.x * 32 + (threadIdx.x >> 3);   // x-quad index, 0..256
    if (j > IW) return;                                       // 257 quads in x
    const int k    = blockIdx.y;                              // y-quad index, 0..256
    const int n    = blockIdx.z;

    // Input patch coords (clamped)
    const int ya = max(k - 1, 0);
    const int yb = min(k, IH - 1);
    const int xa = max(j - 1, 0);
    const int xb = min(j, IW - 1);

    const float4* __restrict__ ibase = in + (long long)n * (IH * IW * C4);
    const float4 vaa = __ldg(ibase + (ya * IW + xa) * C4 + c4);
    const float4 vab = __ldg(ibase + (ya * IW + xb) * C4 + c4);
    const float4 vba = __ldg(ibase + (yb * IW + xa) * C4 + c4);
    const float4 vbb = __ldg(ibase + (yb * IW + xb) * C4 + c4);

    // Separable x-interps: w0 = weight of the xb (right) column
    // column c0 = 2j-1 (odd)  -> w0 = 0.25
    // column c1 = 2j   (even) -> w0 = 0.75
    float4 tL, tR, bL, bR;
    tL.x = 0.75f * vaa.x + 0.25f * vab.x;  tR.x = 0.25f * vaa.x + 0.75f * vab.x;
    tL.y = 0.75f * vaa.y + 0.25f * vab.y;  tR.y = 0.25f * vaa.y + 0.75f * vab.y;
    tL.z = 0.75f * vaa.z + 0.25f * vab.z;  tR.z = 0.25f * vaa.z + 0.75f * vab.z;
    tL.w = 0.75f * vaa.w + 0.25f * vab.w;  tR.w = 0.25f * vaa.w + 0.75f * vab.w;
    bL.x = 0.75f * vba.x + 0.25f * vbb.x;  bR.x = 0.25f * vba.x + 0.75f * vbb.x;
    bL.y = 0.75f * vba.y + 0.25f * vbb.y;  bR.y = 0.25f * vba.y + 0.75f * vbb.y;
    bL.z = 0.75f * vba.z + 0.25f * vbb.z;  bR.z = 0.25f * vba.z + 0.75f * vbb.z;
    bL.w = 0.75f * vba.w + 0.25f * vbb.w;  bR.w = 0.25f * vba.w + 0.75f * vbb.w;

    // Output quad coords (clamped; edge duplicates write the same value)
    const int r0 = max(2 * k - 1, 0);
    const int r1 = min(2 * k, OH - 1);
    const int c0 = max(2 * j - 1, 0);
    const int c1 = min(2 * j, OW - 1);

    float4* __restrict__ obase = out + (long long)n * (OH * OW * C4);

    float4 o;
    // (r0, c0): h0 = 0.25 (weight of bottom row)
    o.x = 0.75f * tL.x + 0.25f * bL.x;
    o.y = 0.75f * tL.y + 0.25f * bL.y;
    o.z = 0.75f * tL.z + 0.25f * bL.z;
    o.w = 0.75f * tL.w + 0.25f * bL.w;
    obase[(r0 * OW + c0) * C4 + c4] = o;

    // (r0, c1)
    o.x = 0.75f * tR.x + 0.25f * bR.x;
    o.y = 0.75f * tR.y + 0.25f * bR.y;
    o.z = 0.75f * tR.z + 0.25f * bR.z;
    o.w = 0.75f * tR.w + 0.25f * bR.w;
    obase[(r0 * OW + c1) * C4 + c4] = o;

    // (r1, c0): h0 = 0.75
    o.x = 0.25f * tL.x + 0.75f * bL.x;
    o.y = 0.25f * tL.y + 0.75f * bL.y;
    o.z = 0.25f * tL.z + 0.75f * bL.z;
    o.w = 0.25f * tL.w + 0.75f * bL.w;
    obase[(r1 * OW + c0) * C4 + c4] = o;

    // (r1, c1)
    o.x = 0.25f * tR.x + 0.75f * bR.x;
    o.y = 0.25f * tR.y + 0.75f * bR.y;
    o.z = 0.25f * tR.z + 0.75f * bR.z;
    o.w = 0.25f * tR.w + 0.75f * bR.w;
    obase[(r1 * OW + c1) * C4 + c4] = o;
}

extern "C" void kernel_launch(void* const* d_in, const int* in_sizes, int n_in,
                              void* d_out, int out_size)
{
    const float4* in  = (const float4*)d_in[0];
    float4*       out = (float4*)d_out;
    // 257 quads per axis (edge quads are degenerate/clamped)
    dim3 block(256, 1, 1);                    // 8 c4 x 32 j
    dim3 grid((IW / 32) + 1, IH + 1, 8);      // (9, 257, 8)
    bilinear2x_quad_kernel<<<grid, block>>>(in, out);
}